// round 8
// baseline (speedup 1.0000x reference)
#include <cuda_runtime.h>
#include <cstdint>

#define BB 64
#define PP 256
#define NN 1000
typedef unsigned long long ull;

__device__ float g_K[BB * NN * 128];
__device__ float g_V[BB * NN * 128];
__device__ float g_Q[BB * PP * 128];

// ---- f32x2 / memory helpers ----
__device__ __forceinline__ ull ffma2(ull a, ull b, ull c) {
    ull d; asm("fma.rn.f32x2 %0,%1,%2,%3;" : "=l"(d) : "l"(a), "l"(b), "l"(c)); return d;
}
__device__ __forceinline__ ull fmul2(ull a, ull b) {
    ull d; asm("mul.rn.f32x2 %0,%1,%2;" : "=l"(d) : "l"(a), "l"(b)); return d;
}
__device__ __forceinline__ ull pack2(float lo, float hi) {
    ull d; asm("mov.b64 %0,{%1,%2};" : "=l"(d) : "f"(lo), "f"(hi)); return d;
}
__device__ __forceinline__ float hadd2(ull a) {
    float lo, hi; asm("mov.b64 {%0,%1},%2;" : "=f"(lo), "=f"(hi) : "l"(a)); return lo + hi;
}
__device__ __forceinline__ void lds2x64(const float* p, ull& a, ull& b) {
    uint32_t ad = (uint32_t)__cvta_generic_to_shared(p);
    asm("ld.shared.v2.b64 {%0,%1},[%2];" : "=l"(a), "=l"(b) : "r"(ad));
}
__device__ __forceinline__ ull lds64(const float* p) {
    uint32_t ad = (uint32_t)__cvta_generic_to_shared(p);
    ull a; asm("ld.shared.b64 %0,[%1];" : "=l"(a) : "r"(ad)); return a;
}
__device__ __forceinline__ void sts64(float* p, ull v) {
    uint32_t ad = (uint32_t)__cvta_generic_to_shared(p);
    asm volatile("st.shared.b64 [%0],%1;" :: "r"(ad), "l"(v));
}
__device__ __forceinline__ void sts128z(float* p) {
    uint32_t ad = (uint32_t)__cvta_generic_to_shared(p);
    asm volatile("st.shared.v4.b32 [%0],{%1,%1,%1,%1};" :: "r"(ad), "r"(0));
}
__device__ __forceinline__ void sts32(float* p, float v) {
    uint32_t ad = (uint32_t)__cvta_generic_to_shared(p);
    asm volatile("st.shared.b32 [%0],%1;" :: "r"(ad), "f"(v));
}
__device__ __forceinline__ void ldg2x64(const float* p, ull& a, ull& b) {
    asm("ld.global.nc.v2.b64 {%0,%1},[%2];" : "=l"(a), "=l"(b) : "l"(p));
}
__device__ __forceinline__ void cp16(float* dst, const float* src) {
    uint32_t d = (uint32_t)__cvta_generic_to_shared(dst);
    asm volatile("cp.async.cg.shared.global [%0],[%1],16;" :: "r"(d), "l"(src));
}
__device__ __forceinline__ void cp4(float* dst, const float* src) {
    uint32_t d = (uint32_t)__cvta_generic_to_shared(dst);
    asm volatile("cp.async.ca.shared.global [%0],[%1],4;" :: "r"(d), "l"(src));
}
__device__ __forceinline__ void cp_commit() { asm volatile("cp.async.commit_group;"); }
template <int N> __device__ __forceinline__ void cp_wait() {
    asm volatile("cp.async.wait_group %0;" :: "n"(N));
}

// ---------------------------------------------------------------------------
// K/V projection (unchanged, measured 118us). 32 rows/block, 256 threads.
// ---------------------------------------------------------------------------
__global__ __launch_bounds__(256) void kv_proj(const float* __restrict__ enc,
                                               const float* __restrict__ Wk,
                                               const float* __restrict__ Wv) {
    __shared__ float xs[32 * 128];
    int t = threadIdx.x;
    int row0 = blockIdx.x * 32;
    const float4* src = (const float4*)(enc + (size_t)row0 * 128);
    float4* xs4 = (float4*)xs;
#pragma unroll
    for (int i = t; i < 1024; i += 256) xs4[i] = src[i];
    __syncthreads();

    int mat = t >> 7, rh = (t >> 6) & 1, cp = t & 63;
    const float* W = mat ? Wv : Wk;
    float* out = mat ? g_V : g_K;
    const float* xb = xs + rh * 2048;

    ull acc[32];
#pragma unroll
    for (int i = 0; i < 32; i++) acc[i] = 0ull;

#pragma unroll 2
    for (int k = 0; k < 128; k += 2) {
        ull w0 = pack2(W[k * 128 + cp], W[(k + 1) * 128 + cp]);
        ull w1 = pack2(W[k * 128 + cp + 64], W[(k + 1) * 128 + cp + 64]);
#pragma unroll
        for (int r = 0; r < 16; r++) {
            ull x = lds64(xb + r * 128 + k);
            acc[r]      = ffma2(x, w0, acc[r]);
            acc[16 + r] = ffma2(x, w1, acc[16 + r]);
        }
    }
#pragma unroll
    for (int r = 0; r < 16; r++) {
        size_t row = (size_t)(row0 + rh * 16 + r) * 128;
        out[row + cp]      = hadd2(acc[r]);
        out[row + cp + 64] = hadd2(acc[16 + r]);
    }
}

// ---------------------------------------------------------------------------
// Q projection (unchanged)
// ---------------------------------------------------------------------------
__global__ __launch_bounds__(256) void q_proj(const float* __restrict__ last,
                                              const float* __restrict__ attr,
                                              const float* __restrict__ Wq) {
    __shared__ float xs[16 * 132];
    int row0 = blockIdx.x * 16;
    int t = threadIdx.x;
#pragma unroll
    for (int i = t; i < 2048; i += 256) {
        int r = i >> 7, c = i & 127;
        xs[r * 132 + c] = last[(size_t)(row0 + r) * 128 + c];
    }
    if (t < 16) xs[t * 132 + 128] = attr[row0 + t];
    __syncthreads();

    int rh = t >> 7, col = t & 127;
    const float* xr = xs + rh * 8 * 132;
    float acc[8] = {0, 0, 0, 0, 0, 0, 0, 0};
#pragma unroll 4
    for (int in = 0; in < 129; in++) {
        float w = Wq[in * 128 + col];
#pragma unroll
        for (int r = 0; r < 8; r++) acc[r] += xr[r * 132 + in] * w;
    }
#pragma unroll
    for (int r = 0; r < 8; r++)
        g_Q[(size_t)(row0 + rh * 8 + r) * 128 + col] = acc[r];
}

// ---------------------------------------------------------------------------
// Fused attention: 64-query tiles, 256 blocks, 2 queries per lane.
// warp = head h; lane owns queries (lane, lane+32) of the tile.
// smem floats (28864 total = 115456 B):
//   om   [0, 8192)      out -> mh in-place alias (stride 128)
//   inv  [8192, 8256)
//   work [8256, 28864)  (20608)
//     phase A: k0 4096 | k1 4096 | v0 4096 | v1 4096 | md0 2112 | md1 2112
//     Wo stage: 16384
//     phase B: enc0 8448 | enc1 8448   (stride 132)
// ---------------------------------------------------------------------------
__global__ __launch_bounds__(256, 2) void attn_kernel(
        const float* __restrict__ enc, const float* __restrict__ mask,
        const float* __restrict__ Wo, const float* __restrict__ bo,
        float* __restrict__ probs) {
    extern __shared__ float sm[];
    float* om    = sm;
    float* inv_s = sm + 8192;
    float* work  = sm + 8256;

    int t = threadIdx.x;
    int b = blockIdx.x >> 2;
    int p0 = (blockIdx.x & 3) * 64;
    int h = t >> 5, lane = t & 31;

    const float* Kb = g_K + (size_t)b * NN * 128;
    const float* Vb = g_V + (size_t)b * NN * 128;
    const float* Mb = mask + (size_t)(b * PP + p0) * NN;

    auto stageA = [&](int chunk) {
        int buf = chunk & 1;
        int base = chunk * 32;
        int nv = NN - base; if (nv > 32) nv = 32;
        float* kd = work + buf * 4096;
        float* vd = work + 8192 + buf * 4096;
        float* md = work + 16384 + buf * 2112;
#pragma unroll
        for (int j = 0; j < 4; j++) {
            int i = t + j * 256;
            int n = i >> 5, seg = i & 31;
            if (n < nv) {
                cp16(kd + n * 128 + seg * 4, Kb + (size_t)(base + n) * 128 + seg * 4);
                cp16(vd + n * 128 + seg * 4, Vb + (size_t)(base + n) * 128 + seg * 4);
            } else {
                sts128z(kd + n * 128 + seg * 4);
                sts128z(vd + n * 128 + seg * 4);
            }
        }
#pragma unroll
        for (int j = 0; j < 8; j++) {
            int i = t + j * 256;
            int p = i >> 5, n = i & 31;
            if (n < nv) cp4(md + p * 33 + n, Mb + (size_t)p * NN + base + n);
            else        sts32(md + p * 33 + n, -1e30f);
        }
    };
    auto stageB = [&](int chunk) {
        int buf = chunk & 1;
        int base = chunk * 64;
        int nv = NN - base; if (nv > 64) nv = 64;
        float* ed = work + buf * 8448;
        const float* Eb = enc + (size_t)b * NN * 128;
#pragma unroll
        for (int j = 0; j < 8; j++) {
            int i = t + j * 256;
            int n = i >> 5, seg = i & 31;
            if (n < nv)
                cp16(ed + n * 132 + seg * 4, Eb + (size_t)(base + n) * 128 + seg * 4);
        }
    };

    // q for both queries (0.25 prescaled)
    ull qA[8], qB[8];
    {
        const float* qp = g_Q + (size_t)(b * PP + p0 + lane) * 128 + h * 16;
        ull c = pack2(0.25f, 0.25f);
#pragma unroll
        for (int j = 0; j < 4; j++) {
            ull a0, a1;
            ldg2x64(qp + 4 * j, a0, a1);
            qA[2 * j]     = fmul2(a0, c);
            qA[2 * j + 1] = fmul2(a1, c);
        }
        const float* qp2 = qp + 32 * 128;
#pragma unroll
        for (int j = 0; j < 4; j++) {
            ull a0, a1;
            ldg2x64(qp2 + 4 * j, a0, a1);
            qB[2 * j]     = fmul2(a0, c);
            qB[2 * j + 1] = fmul2(a1, c);
        }
    }

    float lA = 0.f, lB = 0.f;
    ull accA[8], accB[8];
#pragma unroll
    for (int j = 0; j < 8; j++) { accA[j] = 0ull; accB[j] = 0ull; }

    stageA(0); cp_commit();
    stageA(1); cp_commit();

    // ---- phase A: 32 chunks of 32 keys ----
    for (int c = 0; c < 32; c++) {
        if (c == 31) cp_wait<0>(); else cp_wait<1>();
        __syncthreads();

        int buf = c & 1;
        const float* k_s = work + buf * 4096;
        const float* v_s = work + 8192 + buf * 4096;
        const float* md  = work + 16384 + buf * 2112;
        const float* mA = md + lane * 33;
        const float* mB = md + (lane + 32) * 33;

#pragma unroll 2
        for (int n = 0; n < 32; n++) {
            const float* kp = k_s + n * 128 + h * 16;
            ull k0, k1, k2, k3, k4, k5, k6, k7;
            lds2x64(kp,      k0, k1);
            lds2x64(kp + 4,  k2, k3);
            lds2x64(kp + 8,  k4, k5);
            lds2x64(kp + 12, k6, k7);
            ull dA = fmul2(qA[0], k0);
            dA = ffma2(qA[1], k1, dA); dA = ffma2(qA[2], k2, dA);
            dA = ffma2(qA[3], k3, dA); dA = ffma2(qA[4], k4, dA);
            dA = ffma2(qA[5], k5, dA); dA = ffma2(qA[6], k6, dA);
            dA = ffma2(qA[7], k7, dA);
            ull dB = fmul2(qB[0], k0);
            dB = ffma2(qB[1], k1, dB); dB = ffma2(qB[2], k2, dB);
            dB = ffma2(qB[3], k3, dB); dB = ffma2(qB[4], k4, dB);
            dB = ffma2(qB[5], k5, dB); dB = ffma2(qB[6], k6, dB);
            dB = ffma2(qB[7], k7, dB);
            float wA = __expf(hadd2(dA) + mA[n]);
            float wB = __expf(hadd2(dB) + mB[n]);
            lA += wA; lB += wB;
            const float* vp = v_s + n * 128 + h * 16;
            ull v0, v1, v2, v3, v4, v5, v6, v7;
            lds2x64(vp,      v0, v1);
            lds2x64(vp + 4,  v2, v3);
            lds2x64(vp + 8,  v4, v5);
            lds2x64(vp + 12, v6, v7);
            ull wwA = pack2(wA, wA);
            ull wwB = pack2(wB, wB);
            accA[0] = ffma2(wwA, v0, accA[0]); accA[1] = ffma2(wwA, v1, accA[1]);
            accA[2] = ffma2(wwA, v2, accA[2]); accA[3] = ffma2(wwA, v3, accA[3]);
            accA[4] = ffma2(wwA, v4, accA[4]); accA[5] = ffma2(wwA, v5, accA[5]);
            accA[6] = ffma2(wwA, v6, accA[6]); accA[7] = ffma2(wwA, v7, accA[7]);
            accB[0] = ffma2(wwB, v0, accB[0]); accB[1] = ffma2(wwB, v1, accB[1]);
            accB[2] = ffma2(wwB, v2, accB[2]); accB[3] = ffma2(wwB, v3, accB[3]);
            accB[4] = ffma2(wwB, v4, accB[4]); accB[5] = ffma2(wwB, v5, accB[5]);
            accB[6] = ffma2(wwB, v6, accB[6]); accB[7] = ffma2(wwB, v7, accB[7]);
        }
        __syncthreads();
        if (c + 2 < 32) { stageA(c + 2); cp_commit(); }
    }

    // finalize attention outputs into om (out region)
    {
        float ivA = 1.f / lA, ivB = 1.f / lB;
        ull iA = pack2(ivA, ivA), iB = pack2(ivB, ivB);
        float* oA = om + lane * 128 + h * 16;
        float* oB = om + (lane + 32) * 128 + h * 16;
#pragma unroll
        for (int j = 0; j < 8; j++) {
            sts64(oA + 2 * j, fmul2(accA[j], iA));
            sts64(oB + 2 * j, fmul2(accB[j], iB));
        }
    }
    __syncthreads();

    // stage Wo (64KB) into work
    {
        const float4* Wo4 = (const float4*)Wo;
#pragma unroll
        for (int j = 0; j < 16; j++) {
            int i = t + j * 256;
            cp16(work + i * 4, (const float*)(Wo4 + i));
        }
        cp_commit(); cp_wait<0>();
    }
    __syncthreads();

    // mh = out @ Wo + bo  (in-place in om; thread = 4 rows x 8 e, 2 passes)
    {
        int pg = t >> 4;          // 16 groups -> 4 rows each
        int eg = (t & 15) * 8;
        const float* Wos = work;
#pragma unroll
        for (int pass = 0; pass < 2; pass++) {
            int r0 = 4 * pg + 2 * pass;
            float* x0p = om + r0 * 128;
            float* x1p = x0p + 128;
            ull a0[4], a1[4];
            {
                ull b0, b1, b2, b3;
                ldg2x64(bo + eg, b0, b1);
                ldg2x64(bo + eg + 4, b2, b3);
                a0[0] = b0; a0[1] = b1; a0[2] = b2; a0[3] = b3;
                a1[0] = b0; a1[1] = b1; a1[2] = b2; a1[3] = b3;
            }
#pragma unroll 4
            for (int k = 0; k < 128; k++) {
                float x0 = x0p[k], x1 = x1p[k];
                ull xx0 = pack2(x0, x0), xx1 = pack2(x1, x1);
                const float* wp = Wos + k * 128 + eg;
                ull w0, w1, w2, w3;
                lds2x64(wp, w0, w1);
                lds2x64(wp + 4, w2, w3);
                a0[0] = ffma2(xx0, w0, a0[0]); a0[1] = ffma2(xx0, w1, a0[1]);
                a0[2] = ffma2(xx0, w2, a0[2]); a0[3] = ffma2(xx0, w3, a0[3]);
                a1[0] = ffma2(xx1, w0, a1[0]); a1[1] = ffma2(xx1, w1, a1[1]);
                a1[2] = ffma2(xx1, w2, a1[2]); a1[3] = ffma2(xx1, w3, a1[3]);
            }
            // in-place: this thread is the only reader of rows r0, r0+1
            float* m0 = x0p + eg;
            float* m1 = x1p + eg;
#pragma unroll
            for (int j = 0; j < 4; j++) { sts64(m0 + 2 * j, a0[j]); sts64(m1 + 2 * j, a1[j]); }
        }
    }
    __syncthreads();

    stageB(0); cp_commit();
    stageB(1); cp_commit();

    // ---- phase B: 16 chunks of 64 nodes; warp owns 8 p; thread = 4p x 2n x 2 passes
    int pq = t >> 5, nh = t & 31;
    float rs[2][4];
#pragma unroll
    for (int q = 0; q < 2; q++)
#pragma unroll
        for (int pp = 0; pp < 4; pp++) rs[q][pp] = 0.f;
    float* pout = probs + (size_t)(b * PP + p0) * NN;
    const float inv_se = 0.08838834764831845f;

    for (int c = 0; c < 16; c++) {
        if (c == 15) cp_wait<0>(); else cp_wait<1>();
        __syncthreads();

        int buf = c & 1;
        int base = c * 64;
        int nv = NN - base; if (nv > 64) nv = 64;
        const float* e_s = work + buf * 8448;
        const float* e0p = e_s + nh * 132;
        const float* e1p = e_s + (nh + 32) * 132;

#pragma unroll
        for (int pass = 0; pass < 2; pass++) {
            const float* mrow = om + (8 * pq + 4 * pass) * 128;
            ull a[4][2];
#pragma unroll
            for (int pp = 0; pp < 4; pp++) { a[pp][0] = 0ull; a[pp][1] = 0ull; }

#pragma unroll 4
            for (int k = 0; k < 128; k += 4) {
                ull e00, e01, e10, e11;
                lds2x64(e0p + k, e00, e01);
                lds2x64(e1p + k, e10, e11);
#pragma unroll
                for (int pp = 0; pp < 4; pp++) {
                    ull m0, m1;
                    lds2x64(mrow + pp * 128 + k, m0, m1);
                    a[pp][0] = ffma2(m0, e00, a[pp][0]);
                    a[pp][0] = ffma2(m1, e01, a[pp][0]);
                    a[pp][1] = ffma2(m0, e10, a[pp][1]);
                    a[pp][1] = ffma2(m1, e11, a[pp][1]);
                }
            }
#pragma unroll
            for (int j = 0; j < 2; j++) {
                int n = nh + 32 * j;
                if (n < nv) {
#pragma unroll
                    for (int pp = 0; pp < 4; pp++) {
                        int p = 8 * pq + 4 * pass + pp;
                        float sd = hadd2(a[pp][j]);
                        float x = sd * inv_se;
                        x = fminf(fmaxf(x, -30.f), 30.f);
                        float ex = __expf(-2.f * x);
                        float th = __fdividef(1.f - ex, 1.f + ex);
                        float lg = 10.f * th + Mb[(size_t)p * NN + base + n];
                        float w = __expf(lg - 10.f);
                        rs[pass][pp] += w;
                        pout[(size_t)p * NN + base + n] = w;
                    }
                }
            }
        }
        __syncthreads();
        if (c + 2 < 16) { stageB(c + 2); cp_commit(); }
    }

    // warp-reduce row sums (warp owns its 8 p's entirely)
#pragma unroll
    for (int off = 16; off; off >>= 1) {
#pragma unroll
        for (int q = 0; q < 2; q++)
#pragma unroll
            for (int pp = 0; pp < 4; pp++)
                rs[q][pp] += __shfl_xor_sync(0xFFFFFFFFu, rs[q][pp], off);
    }
    if (nh == 0) {
#pragma unroll
        for (int q = 0; q < 2; q++)
#pragma unroll
            for (int pp = 0; pp < 4; pp++)
                inv_s[8 * pq + 4 * q + pp] = 1.f / rs[q][pp];
    }
    __syncthreads();
#pragma unroll
    for (int p = 0; p < 64; p++) {
        float ivp = inv_s[p];
        for (int i = t; i < NN; i += 256)
            pout[(size_t)p * NN + i] *= ivp;
    }
}

// ---------------------------------------------------------------------------
extern "C" void kernel_launch(void* const* d_in, const int* in_sizes, int n_in,
                              void* d_out, int out_size) {
    const float* enc  = (const float*)d_in[0];
    const float* last = (const float*)d_in[1];
    const float* attr = (const float*)d_in[2];
    const float* mask = (const float*)d_in[3];
    const float* Wq   = (const float*)d_in[4];
    const float* Wk   = (const float*)d_in[5];
    const float* Wv   = (const float*)d_in[6];
    const float* Wo   = (const float*)d_in[7];
    const float* bo   = (const float*)d_in[8];
    float* out = (float*)d_out;

    cudaFuncSetAttribute(attn_kernel,
                         cudaFuncAttributeMaxDynamicSharedMemorySize, 115456);

    kv_proj<<<2000, 256>>>(enc, Wk, Wv);
    q_proj<<<1024, 256>>>(last, attr, Wq);
    attn_kernel<<<256, 256, 115456>>>(enc, mask, Wo, bo, out);
}